// round 3
// baseline (speedup 1.0000x reference)
#include <cuda_runtime.h>
#include <cuda_bf16.h>

#define N_NODES 100000
#define B_DIM   16

// Scratch: transposed x and accumulator, [N, B] layout: one node's 16 batch
// values are 64 contiguous bytes (one L2 row / 2 sectors).
__device__ float g_xt[N_NODES * B_DIM];
__device__ float g_yt[N_NODES * B_DIM];

// ---------------------------------------------------------------------------
// Kernel 1: transpose x [B,N] -> g_xt [N,B], zero g_yt.
// 256 nodes x 16 batches per block, float4 on both sides. N % 4 == 0 assumed
// for vector loads (guarded per-vector).
// ---------------------------------------------------------------------------
__global__ void __launch_bounds__(256)
transpose_zero_kernel(const float* __restrict__ x, int N) {
    __shared__ float tile[16][257];  // [b][n], pad to keep column reads clean
    const int n0 = blockIdx.x * 256;
    const int tid = threadIdx.x;
    const int N4 = N >> 2;           // N divisible by 4

    // Load: 1024 float4s (16 b x 64 quads) by 256 threads, coalesced along n.
    const float4* x4 = (const float4*)x;
    #pragma unroll
    for (int p = 0; p < 4; p++) {
        int idx = p * 256 + tid;     // 0..1023
        int b  = idx >> 6;           // 0..15
        int nq = idx & 63;           // quad within tile
        int gq = (n0 >> 2) + nq;
        float4 v = make_float4(0.f, 0.f, 0.f, 0.f);
        if (gq < N4) v = x4[b * N4 + gq];
        tile[b][4 * nq + 0] = v.x;
        tile[b][4 * nq + 1] = v.y;
        tile[b][4 * nq + 2] = v.z;
        tile[b][4 * nq + 3] = v.w;
    }
    __syncthreads();

    // Store: thread = one node; write its full 16-batch row as 4 float4.
    int nn = n0 + tid;
    if (nn < N) {
        float4* xo = (float4*)&g_xt[nn * B_DIM];
        float4* yo = (float4*)&g_yt[nn * B_DIM];
        #pragma unroll
        for (int q = 0; q < 4; q++) {
            float4 v;
            v.x = tile[4 * q + 0][tid];
            v.y = tile[4 * q + 1][tid];
            v.z = tile[4 * q + 2][tid];
            v.w = tile[4 * q + 3][tid];
            xo[q] = v;
            yo[q] = make_float4(0.f, 0.f, 0.f, 0.f);
        }
    }
}

// ---------------------------------------------------------------------------
// Kernel 2: edge stage, ONE THREAD PER EDGE (all 16 batches in registers).
// Per thread: 5 coalesced scalar loads, 4x LDG.128 gather, 16x (fma,tanh,fma),
// 4x red.global.add.v4.f32.
// ---------------------------------------------------------------------------
__global__ void __launch_bounds__(256)
edge_kernel(const int*   __restrict__ src_idx,
            const int*   __restrict__ dst_idx,
            const float* __restrict__ edge_alpha,
            const float* __restrict__ edge_w,
            const float* __restrict__ edge_b,
            int E) {
    int e = blockIdx.x * blockDim.x + threadIdx.x;
    if (e >= E) return;

    int   s  = src_idx[e];
    int   d  = dst_idx[e];
    float w  = edge_w[e];
    float bb = edge_b[e];
    float a  = edge_alpha[e];

    const float4* xr = (const float4*)&g_xt[s * B_DIM];
    float4 xv0 = xr[0];
    float4 xv1 = xr[1];
    float4 xv2 = xr[2];
    float4 xv3 = xr[3];

    size_t ybase = __cvta_generic_to_global(&g_yt[d * B_DIM]);

    #pragma unroll
    for (int q = 0; q < 4; q++) {
        float4 xv = (q == 0) ? xv0 : (q == 1) ? xv1 : (q == 2) ? xv2 : xv3;
        float l0 = fmaf(w, xv.x, bb);
        float l1 = fmaf(w, xv.y, bb);
        float l2 = fmaf(w, xv.z, bb);
        float l3 = fmaf(w, xv.w, bb);
        float t0, t1, t2, t3;
        asm("tanh.approx.f32 %0, %1;" : "=f"(t0) : "f"(l0));
        asm("tanh.approx.f32 %0, %1;" : "=f"(t1) : "f"(l1));
        asm("tanh.approx.f32 %0, %1;" : "=f"(t2) : "f"(l2));
        asm("tanh.approx.f32 %0, %1;" : "=f"(t3) : "f"(l3));
        float m0 = fmaf(a, t0 - l0, l0);
        float m1 = fmaf(a, t1 - l1, l1);
        float m2 = fmaf(a, t2 - l2, l2);
        float m3 = fmaf(a, t3 - l3, l3);
        asm volatile("red.global.add.v4.f32 [%0], {%1, %2, %3, %4};"
                     :: "l"(ybase + q * 16), "f"(m0), "f"(m1), "f"(m2), "f"(m3)
                     : "memory");
    }
}

// ---------------------------------------------------------------------------
// Kernel 3: node stage + transpose back. 256 nodes x 16 batches per block.
// Reads g_yt rows as float4, math + coalesced float4 stores to out [B,N].
// ---------------------------------------------------------------------------
__global__ void __launch_bounds__(256)
node_kernel(const float* __restrict__ node_alpha,
            const float* __restrict__ node_w,
            const float* __restrict__ node_b,
            float* __restrict__ out, int N) {
    __shared__ float tile[16][257];
    const int n0 = blockIdx.x * 256;
    const int tid = threadIdx.x;
    const int N4 = N >> 2;

    // Load: thread = one node; read its 16-batch row, scatter into tile cols.
    int nn = n0 + tid;
    if (nn < N) {
        const float4* yr = (const float4*)&g_yt[nn * B_DIM];
        #pragma unroll
        for (int q = 0; q < 4; q++) {
            float4 v = yr[q];
            tile[4 * q + 0][tid] = v.x;
            tile[4 * q + 1][tid] = v.y;
            tile[4 * q + 2][tid] = v.z;
            tile[4 * q + 3][tid] = v.w;
        }
    }
    __syncthreads();

    // Store: 1024 float4s (16 b x 64 quads), math per element.
    float4* o4 = (float4*)out;
    #pragma unroll
    for (int p = 0; p < 4; p++) {
        int idx = p * 256 + tid;
        int b  = idx >> 6;
        int nq = idx & 63;
        int gq = (n0 >> 2) + nq;
        if (gq < N4) {
            float4 r;
            #pragma unroll
            for (int k = 0; k < 4; k++) {
                int nl = 4 * nq + k;         // node within tile
                int ng = n0 + nl;            // global node
                float y   = tile[b][nl];
                float w   = node_w[ng];
                float bb  = node_b[ng];
                float a   = node_alpha[ng];
                float lin = fmaf(w, y, bb);
                float th;
                asm("tanh.approx.f32 %0, %1;" : "=f"(th) : "f"(lin));
                float v = fmaf(a, th - lin, lin);
                ((float*)&r)[k] = v;
            }
            o4[b * N4 + gq] = r;
        }
    }
}

// ---------------------------------------------------------------------------
// Input order: x, src_idx, dst_idx, edge_alpha, edge_w, edge_b,
// node_alpha, node_w, node_b. Output: float32 [B, N].
// ---------------------------------------------------------------------------
extern "C" void kernel_launch(void* const* d_in, const int* in_sizes, int n_in,
                              void* d_out, int out_size) {
    const float* x          = (const float*)d_in[0];
    const int*   src_idx    = (const int*)  d_in[1];
    const int*   dst_idx    = (const int*)  d_in[2];
    const float* edge_alpha = (const float*)d_in[3];
    const float* edge_w     = (const float*)d_in[4];
    const float* edge_b     = (const float*)d_in[5];
    const float* node_alpha = (const float*)d_in[6];
    const float* node_w     = (const float*)d_in[7];
    const float* node_b     = (const float*)d_in[8];
    float* out = (float*)d_out;

    const int E = in_sizes[1];
    const int N = in_sizes[6];

    int n_tiles = (N + 255) / 256;

    transpose_zero_kernel<<<n_tiles, 256>>>(x, N);
    edge_kernel<<<(E + 255) / 256, 256>>>(src_idx, dst_idx, edge_alpha,
                                          edge_w, edge_b, E);
    node_kernel<<<n_tiles, 256>>>(node_alpha, node_w, node_b, out, N);
}

// round 4
// speedup vs baseline: 1.4123x; 1.4123x over previous
#include <cuda_runtime.h>
#include <cuda_bf16.h>

#define N_NODES 100000
#define B_DIM   16

// Scratch: transposed x and accumulator, [N, B] layout: one node's 16 batch
// values are 64 contiguous bytes. g_yt is zero-initialized at module load and
// re-zeroed by node_kernel at the end of every launch (primes next replay).
__device__ float g_xt[N_NODES * B_DIM];
__device__ float g_yt[N_NODES * B_DIM];

// ---------------------------------------------------------------------------
// Kernel 1: transpose x [B,N] -> g_xt [N,B]. 64 nodes x 16 batches per block,
// float4 loads and float4 stores. No zeroing (node_kernel owns that).
// ---------------------------------------------------------------------------
__global__ void __launch_bounds__(256)
transpose_kernel(const float* __restrict__ x, int N) {
    __shared__ float tile[16][66];   // stride 66: conflict-free store-path reads
    const int n0 = blockIdx.x * 64;
    const int tid = threadIdx.x;     // 0..255
    const int N4 = N >> 2;

    // Load: 256 float4s = 16 batches x 16 quads (64 nodes), coalesced along n.
    {
        int b  = tid >> 4;           // 0..15
        int nq = tid & 15;           // 0..15
        int gq = (n0 >> 2) + nq;
        float4 v = make_float4(0.f, 0.f, 0.f, 0.f);
        if (gq < N4) v = ((const float4*)x)[b * N4 + gq];
        tile[b][4 * nq + 0] = v.x;
        tile[b][4 * nq + 1] = v.y;
        tile[b][4 * nq + 2] = v.z;
        tile[b][4 * nq + 3] = v.w;
    }
    __syncthreads();

    // Store: thread -> (node, batch-quad); float4, fully coalesced.
    int n = tid >> 2;                // 0..63
    int q = tid & 3;                 // 0..3
    int nn = n0 + n;
    if (nn < N) {
        float4 v;
        v.x = tile[4 * q + 0][n];
        v.y = tile[4 * q + 1][n];
        v.z = tile[4 * q + 2][n];
        v.w = tile[4 * q + 3][n];
        *(float4*)&g_xt[nn * B_DIM + 4 * q] = v;
    }
}

// ---------------------------------------------------------------------------
// Kernel 2: edge stage (identical to R2's proven version).
// One thread per (edge, batch-quad): float4 gather, 4x (fma,tanh,blend),
// one red.global.add.v4.f32. 4 consecutive lanes share one 64B node row.
// ---------------------------------------------------------------------------
__global__ void __launch_bounds__(256)
edge_kernel(const int*   __restrict__ src_idx,
            const int*   __restrict__ dst_idx,
            const float* __restrict__ edge_alpha,
            const float* __restrict__ edge_w,
            const float* __restrict__ edge_b,
            int E) {
    int t = blockIdx.x * blockDim.x + threadIdx.x;
    if (t >= E * 4) return;
    int e = t >> 2;
    int q = t & 3;

    int   s  = src_idx[e];
    int   d  = dst_idx[e];
    float w  = edge_w[e];
    float bb = edge_b[e];
    float a  = edge_alpha[e];

    float4 xv = *(const float4*)&g_xt[s * B_DIM + 4 * q];

    float l0 = fmaf(w, xv.x, bb);
    float l1 = fmaf(w, xv.y, bb);
    float l2 = fmaf(w, xv.z, bb);
    float l3 = fmaf(w, xv.w, bb);

    float t0, t1, t2, t3;
    asm("tanh.approx.f32 %0, %1;" : "=f"(t0) : "f"(l0));
    asm("tanh.approx.f32 %0, %1;" : "=f"(t1) : "f"(l1));
    asm("tanh.approx.f32 %0, %1;" : "=f"(t2) : "f"(l2));
    asm("tanh.approx.f32 %0, %1;" : "=f"(t3) : "f"(l3));

    float m0 = fmaf(a, t0 - l0, l0);
    float m1 = fmaf(a, t1 - l1, l1);
    float m2 = fmaf(a, t2 - l2, l2);
    float m3 = fmaf(a, t3 - l3, l3);

    size_t gaddr = __cvta_generic_to_global(&g_yt[d * B_DIM + 4 * q]);
    asm volatile("red.global.add.v4.f32 [%0], {%1, %2, %3, %4};"
                 :: "l"(gaddr), "f"(m0), "f"(m1), "f"(m2), "f"(m3)
                 : "memory");
}

// ---------------------------------------------------------------------------
// Kernel 3: node stage + transpose back + RE-ZERO g_yt for the next replay.
// 64 nodes x 16 batches per block.
// ---------------------------------------------------------------------------
__global__ void __launch_bounds__(256)
node_kernel(const float* __restrict__ node_alpha,
            const float* __restrict__ node_w,
            const float* __restrict__ node_b,
            float* __restrict__ out, int N) {
    __shared__ float tile[16][66];
    const int n0 = blockIdx.x * 64;
    const int tid = threadIdx.x;
    const int N4 = N >> 2;

    // Load: thread -> (node, batch-quad); float4 read of g_yt, then zero it.
    {
        int n = tid >> 2;
        int q = tid & 3;
        int nn = n0 + n;
        float4 v = make_float4(0.f, 0.f, 0.f, 0.f);
        if (nn < N) {
            float4* yp = (float4*)&g_yt[nn * B_DIM + 4 * q];
            v = *yp;
            *yp = make_float4(0.f, 0.f, 0.f, 0.f);   // prime next replay
        }
        tile[4 * q + 0][n] = v.x;
        tile[4 * q + 1][n] = v.y;
        tile[4 * q + 2][n] = v.z;
        tile[4 * q + 3][n] = v.w;
    }
    __syncthreads();

    // Store: 256 float4s = 16 batches x 16 quads, coalesced along n.
    {
        int b  = tid >> 4;
        int nq = tid & 15;
        int gq = (n0 >> 2) + nq;
        if (gq < N4) {
            float4 r;
            #pragma unroll
            for (int k = 0; k < 4; k++) {
                int nl = 4 * nq + k;
                int ng = n0 + nl;
                float y   = tile[b][nl];
                float w   = node_w[ng];
                float bb  = node_b[ng];
                float a   = node_alpha[ng];
                float lin = fmaf(w, y, bb);
                float th;
                asm("tanh.approx.f32 %0, %1;" : "=f"(th) : "f"(lin));
                ((float*)&r)[k] = fmaf(a, th - lin, lin);
            }
            ((float4*)out)[b * N4 + gq] = r;
        }
    }
}

// ---------------------------------------------------------------------------
// Input order: x, src_idx, dst_idx, edge_alpha, edge_w, edge_b,
// node_alpha, node_w, node_b. Output: float32 [B, N].
// ---------------------------------------------------------------------------
extern "C" void kernel_launch(void* const* d_in, const int* in_sizes, int n_in,
                              void* d_out, int out_size) {
    const float* x          = (const float*)d_in[0];
    const int*   src_idx    = (const int*)  d_in[1];
    const int*   dst_idx    = (const int*)  d_in[2];
    const float* edge_alpha = (const float*)d_in[3];
    const float* edge_w     = (const float*)d_in[4];
    const float* edge_b     = (const float*)d_in[5];
    const float* node_alpha = (const float*)d_in[6];
    const float* node_w     = (const float*)d_in[7];
    const float* node_b     = (const float*)d_in[8];
    float* out = (float*)d_out;

    const int E = in_sizes[1];
    const int N = in_sizes[6];

    int n_tiles = (N + 63) / 64;

    transpose_kernel<<<n_tiles, 256>>>(x, N);

    int total = E * 4;
    edge_kernel<<<(total + 255) / 256, 256>>>(src_idx, dst_idx, edge_alpha,
                                              edge_w, edge_b, E);

    node_kernel<<<n_tiles, 256>>>(node_alpha, node_w, node_b, out, N);
}

// round 5
// speedup vs baseline: 1.5833x; 1.1211x over previous
#include <cuda_runtime.h>
#include <cuda_bf16.h>

#define N_NODES 100000
#define B_DIM   16

// Scratch: transposed x and accumulator, [N, B] layout so one edge's 16
// batch lanes are 64 contiguous bytes.
__device__ float g_xt[N_NODES * B_DIM];
__device__ float g_yt[N_NODES * B_DIM];

// ---------------------------------------------------------------------------
// Kernel 1: transpose x [B,N] -> g_xt [N,B], and zero g_yt (zeroing here,
// right before the edge kernel's atomics, keeps accumulator lines hot/dirty
// in L2 — proven load-bearing in R2 vs R4).
// Tile: 64 nodes x 16 batches per block (256 threads), float4 loads.
// ---------------------------------------------------------------------------
__global__ void __launch_bounds__(256)
transpose_zero_kernel(const float* __restrict__ x, int N) {
    __shared__ float tile[16][67];   // stride 67 to limit bank conflicts
    const int n0 = blockIdx.x * 64;
    const int tid = threadIdx.x;     // 0..255
    const int N4 = N >> 2;           // N divisible by 4 (100000 / 4)

    // Load: 256 float4s = 16 batches x 16 quads (64 nodes), coalesced along n.
    {
        int b  = tid >> 4;           // 0..15
        int nq = tid & 15;           // 0..15
        int gq = (n0 >> 2) + nq;
        float4 v = make_float4(0.f, 0.f, 0.f, 0.f);
        if (gq < N4) v = ((const float4*)x)[b * N4 + gq];
        tile[b][4 * nq + 0] = v.x;
        tile[b][4 * nq + 1] = v.y;
        tile[b][4 * nq + 2] = v.z;
        tile[b][4 * nq + 3] = v.w;
    }
    __syncthreads();

    // Store: thread -> (node, batch-quad). Writes float4, fully coalesced.
    int n = tid >> 2;        // 0..63
    int q = tid & 3;         // 0..3
    int nn = n0 + n;
    if (nn < N) {
        float4 v;
        v.x = tile[4 * q + 0][n];
        v.y = tile[4 * q + 1][n];
        v.z = tile[4 * q + 2][n];
        v.w = tile[4 * q + 3][n];
        *(float4*)&g_xt[nn * B_DIM + 4 * q] = v;
        *(float4*)&g_yt[nn * B_DIM + 4 * q] = make_float4(0.f, 0.f, 0.f, 0.f);
    }
}

// ---------------------------------------------------------------------------
// Kernel 2: edge stage (R2's proven version, untouched).
// One thread per (edge, batch-quad): float4 gather, 4x (fma, tanh, blend),
// ONE red.global.add.v4.f32.
// ---------------------------------------------------------------------------
__global__ void __launch_bounds__(256)
edge_kernel(const int*   __restrict__ src_idx,
            const int*   __restrict__ dst_idx,
            const float* __restrict__ edge_alpha,
            const float* __restrict__ edge_w,
            const float* __restrict__ edge_b,
            int E) {
    int t = blockIdx.x * blockDim.x + threadIdx.x;
    if (t >= E * 4) return;
    int e = t >> 2;
    int q = t & 3;

    int   s  = src_idx[e];
    int   d  = dst_idx[e];
    float w  = edge_w[e];
    float bb = edge_b[e];
    float a  = edge_alpha[e];

    float4 xv = *(const float4*)&g_xt[s * B_DIM + 4 * q];

    float l0 = fmaf(w, xv.x, bb);
    float l1 = fmaf(w, xv.y, bb);
    float l2 = fmaf(w, xv.z, bb);
    float l3 = fmaf(w, xv.w, bb);

    float t0, t1, t2, t3;
    asm("tanh.approx.f32 %0, %1;" : "=f"(t0) : "f"(l0));
    asm("tanh.approx.f32 %0, %1;" : "=f"(t1) : "f"(l1));
    asm("tanh.approx.f32 %0, %1;" : "=f"(t2) : "f"(l2));
    asm("tanh.approx.f32 %0, %1;" : "=f"(t3) : "f"(l3));

    float m0 = fmaf(a, t0 - l0, l0);
    float m1 = fmaf(a, t1 - l1, l1);
    float m2 = fmaf(a, t2 - l2, l2);
    float m3 = fmaf(a, t3 - l3, l3);

    size_t gaddr = __cvta_generic_to_global(&g_yt[d * B_DIM + 4 * q]);
    asm volatile("red.global.add.v4.f32 [%0], {%1, %2, %3, %4};"
                 :: "l"(gaddr), "f"(m0), "f"(m1), "f"(m2), "f"(m3)
                 : "memory");
}

// ---------------------------------------------------------------------------
// Kernel 3: node stage + transpose back (R2's proven version, untouched).
// Tile: 64 nodes x 16 batches per block, float4 reads of g_yt, no zeroing.
// ---------------------------------------------------------------------------
__global__ void __launch_bounds__(256)
node_kernel(const float* __restrict__ node_alpha,
            const float* __restrict__ node_w,
            const float* __restrict__ node_b,
            float* __restrict__ out, int N) {
    __shared__ float tile[16][67];
    const int n0 = blockIdx.x * 64;
    const int tid = threadIdx.x;

    // Load: thread -> (node, batch-quad), float4 coalesced read of g_yt.
    {
        int n = tid >> 2;
        int q = tid & 3;
        int nn = n0 + n;
        float4 v = make_float4(0.f, 0.f, 0.f, 0.f);
        if (nn < N) v = *(const float4*)&g_yt[nn * B_DIM + 4 * q];
        tile[4 * q + 0][n] = v.x;
        tile[4 * q + 1][n] = v.y;
        tile[4 * q + 2][n] = v.z;
        tile[4 * q + 3][n] = v.w;
    }
    __syncthreads();

    // Store: 4 passes, each covers 4 batch rows x 64 nodes, coalesced along n.
    #pragma unroll
    for (int p = 0; p < 4; p++) {
        int b = p * 4 + (tid >> 6);
        int n = tid & 63;
        int nn = n0 + n;
        if (nn < N) {
            float y   = tile[b][n];
            float w   = node_w[nn];
            float bb  = node_b[nn];
            float a   = node_alpha[nn];
            float lin = fmaf(w, y, bb);
            float th;
            asm("tanh.approx.f32 %0, %1;" : "=f"(th) : "f"(lin));
            out[b * N + nn] = fmaf(a, th - lin, lin);
        }
    }
}

// ---------------------------------------------------------------------------
// Input order: x, src_idx, dst_idx, edge_alpha, edge_w, edge_b,
// node_alpha, node_w, node_b. Output: float32 [B, N].
// ---------------------------------------------------------------------------
extern "C" void kernel_launch(void* const* d_in, const int* in_sizes, int n_in,
                              void* d_out, int out_size) {
    const float* x          = (const float*)d_in[0];
    const int*   src_idx    = (const int*)  d_in[1];
    const int*   dst_idx    = (const int*)  d_in[2];
    const float* edge_alpha = (const float*)d_in[3];
    const float* edge_w     = (const float*)d_in[4];
    const float* edge_b     = (const float*)d_in[5];
    const float* node_alpha = (const float*)d_in[6];
    const float* node_w     = (const float*)d_in[7];
    const float* node_b     = (const float*)d_in[8];
    float* out = (float*)d_out;

    const int E = in_sizes[1];
    const int N = in_sizes[6];

    int n_tiles = (N + 63) / 64;

    transpose_zero_kernel<<<n_tiles, 256>>>(x, N);

    int total = E * 4;
    edge_kernel<<<(total + 255) / 256, 256>>>(src_idx, dst_idx, edge_alpha,
                                              edge_w, edge_b, E);

    node_kernel<<<n_tiles, 256>>>(node_alpha, node_w, node_b, out, N);
}